// round 8
// baseline (speedup 1.0000x reference)
#include <cuda_runtime.h>

// Grouped mean over skeleton nodes:
//   in  : [32, 512, 21, 256] f32   (bt = 16384 rows of 21*256)
//   out : [32, 512, 10, 256] f32
// NODE_MAP = [[1,2],[3,4],[5,6],[7,8],[0,9],[10,11,12],[13,14],[15,16],[17,18],[19,20]]
//
// v8 (256-bit) loads/stores + unroll-2: each thread produces two 32B output
// chunks, loads front-batched for max in-flight bytes per warp.
// total8 = 32*512*10*32 = 1,310,720 v8 outputs; divisible by 512 -> no tail.

__constant__ int   c_n0[10]    = {1, 3, 5, 7, 0, 10, 13, 15, 17, 19};
__constant__ int   c_n1[10]    = {2, 4, 6, 8, 9, 11, 14, 16, 18, 20};
__constant__ int   c_n2[10]    = {-1, -1, -1, -1, -1, 12, -1, -1, -1, -1};
__constant__ float c_scale[10] = {0.5f, 0.5f, 0.5f, 0.5f, 0.5f,
                                  1.0f / 3.0f, 0.5f, 0.5f, 0.5f, 0.5f};

static constexpr int C8 = 32;   // 256 f32 / 8 per node row (32B units)

struct f8 { float v[8]; };

__device__ __forceinline__ f8 ld_cs8(const float* p) {
    f8 r;
    asm volatile("ld.global.cs.v8.f32 {%0,%1,%2,%3,%4,%5,%6,%7}, [%8];"
                 : "=f"(r.v[0]), "=f"(r.v[1]), "=f"(r.v[2]), "=f"(r.v[3]),
                   "=f"(r.v[4]), "=f"(r.v[5]), "=f"(r.v[6]), "=f"(r.v[7])
                 : "l"(p));
    return r;
}
__device__ __forceinline__ void st_cs8(float* p, const f8& r) {
    asm volatile("st.global.cs.v8.f32 [%0], {%1,%2,%3,%4,%5,%6,%7,%8};"
                 :: "l"(p),
                    "f"(r.v[0]), "f"(r.v[1]), "f"(r.v[2]), "f"(r.v[3]),
                    "f"(r.v[4]), "f"(r.v[5]), "f"(r.v[6]), "f"(r.v[7])
                 : "memory");
}

__global__ __launch_bounds__(256)
void s_down_sampling_kernel(const float* __restrict__ in,
                            float* __restrict__ out)
{
    int stride = blockDim.x * gridDim.x;
    int i0 = blockIdx.x * blockDim.x + threadIdx.x;
    int i1 = i0 + stride;

    // ---- addressing for both outputs ----
    const float* pa[2];
    const float* pb[2];
    const float* pc[2];
    float sc[2];
    int idxs[2] = {i0, i1};

    #pragma unroll
    for (int u = 0; u < 2; u++) {
        int idx = idxs[u];
        int c8  = idx & (C8 - 1);
        int tmp = idx >> 5;          // bt*10 + m
        int m   = tmp % 10;
        int bt  = tmp / 10;
        const float* row = in + (long long)bt * (21 * 256);
        int coff = c8 * 8;
        pa[u] = row + c_n0[m] * 256 + coff;
        pb[u] = row + c_n1[m] * 256 + coff;
        int n2 = c_n2[m];
        pc[u] = (n2 >= 0) ? (row + n2 * 256 + coff) : nullptr;
        sc[u] = c_scale[m];
    }

    // ---- front-batched loads: up to 6 outstanding 256-bit LDGs ----
    f8 a0 = ld_cs8(pa[0]);
    f8 b0 = ld_cs8(pb[0]);
    f8 a1 = ld_cs8(pa[1]);
    f8 b1 = ld_cs8(pb[1]);

    f8 r0, r1;
    if (pc[0]) {
        f8 c0 = ld_cs8(pc[0]);
        #pragma unroll
        for (int i = 0; i < 8; i++)
            r0.v[i] = (a0.v[i] + b0.v[i] + c0.v[i]) * sc[0];
    } else {
        #pragma unroll
        for (int i = 0; i < 8; i++)
            r0.v[i] = (a0.v[i] + b0.v[i]) * sc[0];
    }
    st_cs8(out + (long long)i0 * 8, r0);

    if (pc[1]) {
        f8 c1 = ld_cs8(pc[1]);
        #pragma unroll
        for (int i = 0; i < 8; i++)
            r1.v[i] = (a1.v[i] + b1.v[i] + c1.v[i]) * sc[1];
    } else {
        #pragma unroll
        for (int i = 0; i < 8; i++)
            r1.v[i] = (a1.v[i] + b1.v[i]) * sc[1];
    }
    st_cs8(out + (long long)i1 * 8, r1);
}

extern "C" void kernel_launch(void* const* d_in, const int* in_sizes, int n_in,
                              void* d_out, int out_size)
{
    const float* in  = (const float*)d_in[0];
    float*       out = (float*)d_out;

    int total8  = out_size / 8;            // 1,310,720
    int threads = 256;
    int blocks  = total8 / (threads * 2);  // 2560, exact cover
    s_down_sampling_kernel<<<blocks, threads>>>(in, out);
}

// round 9
// speedup vs baseline: 1.0142x; 1.0142x over previous
#include <cuda_runtime.h>

// Grouped mean over skeleton nodes:
//   in  : [32, 512, 21, 256] f32   (bt = 16384 rows of 21*256)
//   out : [32, 512, 10, 256] f32
// NODE_MAP = [[1,2],[3,4],[5,6],[7,8],[0,9],[10,11,12],[13,14],[15,16],[17,18],[19,20]]
//
// FINAL (R7 config — best measured: kernel 69.1us, 6.77 TB/s, DRAM 85.5%):
//   * 256-bit v8 loads/stores (sm_100+): halves LSU/L1tex wavefronts per byte
//     vs float4 (measured: issue 19.9% -> 13.4%, kernel 72.3 -> 69.1 us).
//   * unroll-1, regs=32, occ ~79%: occupancy is the dominant MLP source;
//     unroll-2/4 variants at both widths regressed via register pressure
//     (40-41 regs -> occ 53-61% -> 71-74 us).
//   * .cs evict-first: 520 MB zero-reuse footprint vs 126 MB L2.
// Bytes at the algorithmic floor: 352 MB read + 168 MB write, each input
// element read exactly once. This is the mixed-stream HBM plateau.
//
// total8 = 32*512*10*32 = 1,310,720 v8 outputs; divisible by 256 -> no tail.

__constant__ int   c_n0[10]    = {1, 3, 5, 7, 0, 10, 13, 15, 17, 19};
__constant__ int   c_n1[10]    = {2, 4, 6, 8, 9, 11, 14, 16, 18, 20};
__constant__ int   c_n2[10]    = {-1, -1, -1, -1, -1, 12, -1, -1, -1, -1};
__constant__ float c_scale[10] = {0.5f, 0.5f, 0.5f, 0.5f, 0.5f,
                                  1.0f / 3.0f, 0.5f, 0.5f, 0.5f, 0.5f};

static constexpr int C8      = 32;        // 256 f32 / 8 per node row (32B units)
static constexpr int IN_ROW8 = 21 * C8;   // 672 v8 per bt row (input)

struct f8 { float v[8]; };

// 256-bit evict-first streaming load/store (sm_100+).
__device__ __forceinline__ f8 ld_cs8(const float* p) {
    f8 r;
    asm volatile("ld.global.cs.v8.f32 {%0,%1,%2,%3,%4,%5,%6,%7}, [%8];"
                 : "=f"(r.v[0]), "=f"(r.v[1]), "=f"(r.v[2]), "=f"(r.v[3]),
                   "=f"(r.v[4]), "=f"(r.v[5]), "=f"(r.v[6]), "=f"(r.v[7])
                 : "l"(p));
    return r;
}
__device__ __forceinline__ void st_cs8(float* p, const f8& r) {
    asm volatile("st.global.cs.v8.f32 [%0], {%1,%2,%3,%4,%5,%6,%7,%8};"
                 :: "l"(p),
                    "f"(r.v[0]), "f"(r.v[1]), "f"(r.v[2]), "f"(r.v[3]),
                    "f"(r.v[4]), "f"(r.v[5]), "f"(r.v[6]), "f"(r.v[7])
                 : "memory");
}

__global__ __launch_bounds__(256)
void s_down_sampling_kernel(const float* __restrict__ in,
                            float* __restrict__ out)
{
    int idx = blockIdx.x * blockDim.x + threadIdx.x;   // v8 output index

    int c8  = idx & (C8 - 1);
    int tmp = idx >> 5;              // bt*10 + m
    int m   = tmp % 10;
    int bt  = tmp / 10;

    const float* row = in + (long long)bt * (IN_ROW8 * 8);
    int coff = c8 * 8;

    f8 a = ld_cs8(row + c_n0[m] * 256 + coff);
    f8 b = ld_cs8(row + c_n1[m] * 256 + coff);

    float s = c_scale[m];
    f8 r;

    int n2 = c_n2[m];
    if (n2 >= 0) {
        f8 c = ld_cs8(row + n2 * 256 + coff);
        #pragma unroll
        for (int i = 0; i < 8; i++)
            r.v[i] = (a.v[i] + b.v[i] + c.v[i]) * s;
    } else {
        #pragma unroll
        for (int i = 0; i < 8; i++)
            r.v[i] = (a.v[i] + b.v[i]) * s;
    }

    st_cs8(out + (long long)idx * 8, r);
}

extern "C" void kernel_launch(void* const* d_in, const int* in_sizes, int n_in,
                              void* d_out, int out_size)
{
    const float* in  = (const float*)d_in[0];
    float*       out = (float*)d_out;

    int total8  = out_size / 8;      // 1,310,720
    int threads = 256;
    int blocks  = total8 / threads;  // 5120, exact cover
    s_down_sampling_kernel<<<blocks, threads>>>(in, out);
}